// round 9
// baseline (speedup 1.0000x reference)
#include <cuda_runtime.h>
#include <cuda_bf16.h>
#include <cstdint>
#include <math.h>

#define Bsz 512
#define Ssz 256
#define Esz 256
#define Hsz 512
#define Gsz 1536
#define Lsz 8
#define MROWS (Ssz * Bsz)
#define NCTA 128

// ---------------- device-global scratch (no runtime alloc) ------------------
__device__ __align__(16) float g_gi[(size_t)MROWS * Gsz];
__device__ __align__(16) float g_hf[Bsz * Hsz];          // final h only
__device__ __align__(16) __nv_bfloat16 g_hb_hi[2][Bsz * Hsz];
__device__ __align__(16) __nv_bfloat16 g_hb_lo[2][Bsz * Hsz];
__device__ __align__(16) __nv_bfloat16 g_x_hi[(size_t)MROWS * Esz];
__device__ __align__(16) __nv_bfloat16 g_x_lo[(size_t)MROWS * Esz];
__device__ __align__(16) __nv_bfloat16 g_whh_hi[Gsz * Hsz];
__device__ __align__(16) __nv_bfloat16 g_whh_lo[Gsz * Hsz];
__device__ __align__(16) __nv_bfloat16 g_wih_hi[Gsz * Esz];
__device__ __align__(16) __nv_bfloat16 g_wih_lo[Gsz * Esz];
__device__ __align__(8) unsigned int g_flags[8][16];   // per (b-group, jy) step counter

// ---------------- PTX helpers (base-target only) -----------------------------
__device__ __forceinline__ uint32_t smem_u32(const void* p) {
    uint32_t a;
    asm("{ .reg .u64 t; cvta.to.shared.u64 t, %1; cvt.u32.u64 %0, t; }" : "=r"(a) : "l"(p));
    return a;
}
__device__ __forceinline__ void cp16(uint32_t dst, const void* src) {
    asm volatile("cp.async.cg.shared.global [%0], [%1], 16;" :: "r"(dst), "l"(src));
}
#define CP_COMMIT() asm volatile("cp.async.commit_group;" ::: "memory")
#define CP_WAIT(n)  asm volatile("cp.async.wait_group %0;" :: "n"(n) : "memory")

#define LDMX4(r, addr) \
    asm volatile("ldmatrix.sync.aligned.m8n8.x4.shared.b16 {%0,%1,%2,%3}, [%4];" \
        : "=r"((r)[0]), "=r"((r)[1]), "=r"((r)[2]), "=r"((r)[3]) : "r"(addr))

#define MMA_BF16(c, a, b0, b1) \
    asm volatile("mma.sync.aligned.m16n8k16.row.col.f32.bf16.bf16.f32 " \
        "{%0,%1,%2,%3}, {%4,%5,%6,%7}, {%8,%9}, {%0,%1,%2,%3};" \
        : "+f"((c)[0]), "+f"((c)[1]), "+f"((c)[2]), "+f"((c)[3]) \
        : "r"((a)[0]), "r"((a)[1]), "r"((a)[2]), "r"((a)[3]), "r"(b0), "r"(b1))

#define MBAR_INIT(mb, c) \
    asm volatile("mbarrier.init.shared.b64 [%0], %1;" :: "r"((uint32_t)(mb)), "r"((uint32_t)(c)) : "memory")
#define MBAR_ARRIVE(mb) \
    asm volatile("mbarrier.arrive.shared.b64 _, [%0];" :: "r"((uint32_t)(mb)) : "memory")
#define CP_ASYNC_MBAR_ARRIVE(mb) \
    asm volatile("cp.async.mbarrier.arrive.noinc.shared.b64 [%0];" :: "r"((uint32_t)(mb)) : "memory")

#define MBAR_WAIT(mb, par) do { \
    uint32_t _m = (uint32_t)(mb), _p = (uint32_t)(par), _d; \
    asm volatile("{\n\t.reg .pred p;\n\t" \
        "mbarrier.try_wait.parity.acquire.cta.shared::cta.b64 p, [%1], %2;\n\t" \
        "selp.b32 %0, 1, 0, p;\n\t}" : "=r"(_d) : "r"(_m), "r"(_p) : "memory"); \
    if (!_d) { \
        asm volatile("{\n\t.reg .pred P1;\n\t" \
            "WL_%=:\n\t" \
            "mbarrier.try_wait.parity.acquire.cta.shared::cta.b64 P1, [%0], %1, 0x989680;\n\t" \
            "@P1 bra.uni WD_%=;\n\t" \
            "bra.uni WL_%=;\n\t" \
            "WD_%=:\n\t}" :: "r"(_m), "r"(_p) : "memory"); \
    } \
} while (0)

// wait until both packed u32 counters reach s (every calling thread polls)
__device__ __forceinline__ void poll_pair(const unsigned long long* p, unsigned int s) {
    if (s == 0) return;
    unsigned long long v;
    do {
        asm volatile("ld.acquire.gpu.u64 %0, [%1];" : "=l"(v) : "l"(p));
    } while ((unsigned int)(v & 0xffffffffu) < s || (unsigned int)(v >> 32) < s);
}

// ---------------- split helpers ----------------------------------------------
__device__ __forceinline__ void split2(float v, __nv_bfloat16& h, __nv_bfloat16& l) {
    h = __float2bfloat16_rn(v);
    l = __float2bfloat16_rn(v - __bfloat162float(h));
}
__device__ __forceinline__ void split_store4(float4 v, __nv_bfloat16* dh, __nv_bfloat16* dl) {
    __nv_bfloat16 h0,l0,h1,l1,h2,l2,h3,l3;
    split2(v.x,h0,l0); split2(v.y,h1,l1); split2(v.z,h2,l2); split2(v.w,h3,l3);
    __nv_bfloat162 p;
    p.x=h0; p.y=h1; ((__nv_bfloat162*)dh)[0]=p;
    p.x=h2; p.y=h3; ((__nv_bfloat162*)dh)[1]=p;
    p.x=l0; p.y=l1; ((__nv_bfloat162*)dl)[0]=p;
    p.x=l2; p.y=l3; ((__nv_bfloat162*)dl)[1]=p;
}

// ---------------------------------------------------------------------------
// prep: x split, W_hh split, W_ih split, h0/flags init, one launch
// ---------------------------------------------------------------------------
__global__ void prep_kernel(const float* __restrict__ x,
                            const float* __restrict__ W_hh,
                            const float* __restrict__ W_ih) {
    int blk = blockIdx.x, tid = threadIdx.x;
    if (blk < 32768) {
        size_t t = (size_t)blk * 256 + tid;
        size_t m = t >> 6;
        int e4 = (int)(t & 63) << 2;
        int s = (int)(m >> 9), b = (int)(m & 511);
        float4 v = *(const float4*)(x + ((size_t)b * Ssz + s) * Esz + e4);
        split_store4(v, g_x_hi + m * Esz + e4, g_x_lo + m * Esz + e4);
    } else if (blk < 33536) {
        int t = (blk - 32768) * 256 + tid;
        float4 v = *(const float4*)(W_hh + (size_t)t * 4);
        split_store4(v, g_whh_hi + (size_t)t * 4, g_whh_lo + (size_t)t * 4);
    } else if (blk < 33920) {
        int t = (blk - 33536) * 256 + tid;
        float4 v = *(const float4*)(W_ih + (size_t)t * 4);
        split_store4(v, g_wih_hi + (size_t)t * 4, g_wih_lo + (size_t)t * 4);
    } else {
        int i = (blk - 33920) * 256 + tid;   // < Bsz*Hsz/2
        __nv_bfloat162 z;
        z.x = __float2bfloat16_rn(0.0f); z.y = z.x;
        ((__nv_bfloat162*)g_hb_hi[0])[i] = z;
        ((__nv_bfloat162*)g_hb_lo[0])[i] = z;
        if (blk == 33920 && tid < 128) ((unsigned int*)g_flags)[tid] = 0u;
    }
}

// ---------------------------------------------------------------------------
// gi GEMM (HMMA): R7 version (single 72KB buffer, 3 CTAs/SM). Known-good.
// ---------------------------------------------------------------------------
#define GI_SMEM 73728
#define GA_HI 0
#define GA_LO 18432
#define GB_HI 36864
#define GB_LO 55296

__global__ void __launch_bounds__(256) gi_mma_kernel(const float* __restrict__ b_ih) {
    extern __shared__ __align__(16) char dsm[];
    __shared__ float s_bias[128];
    uint32_t sbase = smem_u32(dsm);
    int tid = threadIdx.x, wid = tid >> 5, lane = tid & 31;
    int n0 = blockIdx.x * 128;
    int m0 = blockIdx.y * 128;
    if (tid < 128) s_bias[tid] = b_ih[n0 + tid];

    int m_warp = (wid & 1) * 64;
    int n_warp = (wid >> 1) * 32;

    float acc[4][4][4];
#pragma unroll
    for (int mi = 0; mi < 4; mi++)
#pragma unroll
        for (int ni = 0; ni < 4; ni++)
#pragma unroll
            for (int e = 0; e < 4; e++) acc[mi][ni][e] = 0.0f;

    for (int c = 0; c < 4; c++) {
        int k0 = c * 64;
        for (int i = tid; i < 4096; i += 256) {
            const __nv_bfloat16* sp;
            uint32_t dst;
            int half = (i >> 10) & 1;
            int idx = i & 1023;
            int row = idx >> 3, seg = idx & 7;
            if (i < 2048) {
                sp = (half ? g_x_lo : g_x_hi) + ((size_t)(m0 + row)) * Esz + k0 + seg * 8;
                dst = sbase + (half ? GA_LO : GA_HI) + (uint32_t)(row * 144 + seg * 16);
            } else {
                sp = (half ? g_wih_lo : g_wih_hi) + ((size_t)(n0 + row)) * Esz + k0 + seg * 8;
                dst = sbase + (half ? GB_LO : GB_HI) + (uint32_t)(row * 144 + seg * 16);
            }
            cp16(dst, sp);
        }
        CP_COMMIT();
        CP_WAIT(0);
        __syncthreads();
#pragma unroll
        for (int kk = 0; kk < 4; kk++) {
            int kb = kk * 32;
            uint32_t fa[2][4][4];
#pragma unroll
            for (int mi = 0; mi < 4; mi++) {
                uint32_t arow = (uint32_t)(m_warp + mi * 16 + (lane & 15));
                uint32_t aoff = arow * 144 + kb + ((lane >> 4) << 4);
                LDMX4(fa[0][mi], sbase + GA_HI + aoff);
                LDMX4(fa[1][mi], sbase + GA_LO + aoff);
            }
            uint32_t fb[2][2][4];
#pragma unroll
            for (int p = 0; p < 2; p++) {
                uint32_t brow = (uint32_t)(n_warp + p * 16 + (lane & 7) + ((lane >> 4) << 3));
                uint32_t boff = brow * 144 + kb + (((lane >> 3) & 1) << 4);
                LDMX4(fb[0][p], sbase + GB_HI + boff);
                LDMX4(fb[1][p], sbase + GB_LO + boff);
            }
#pragma unroll
            for (int t = 0; t < 3; t++) {
                int sa = (t == 2) ? 1 : 0, sb = (t == 1) ? 1 : 0;
#pragma unroll
                for (int mi = 0; mi < 4; mi++)
#pragma unroll
                    for (int ni = 0; ni < 4; ni++)
                        MMA_BF16(acc[mi][ni], fa[sa][mi],
                                 fb[sb][ni >> 1][(ni & 1) * 2],
                                 fb[sb][ni >> 1][(ni & 1) * 2 + 1]);
            }
        }
        __syncthreads();
    }

#pragma unroll
    for (int mi = 0; mi < 4; mi++) {
        int m = m0 + m_warp + mi * 16 + (lane >> 2);
#pragma unroll
        for (int ni = 0; ni < 4; ni++) {
            int nl = n_warp + ni * 8 + (lane & 3) * 2;
            float2 v0 = make_float2(acc[mi][ni][0] + s_bias[nl],
                                    acc[mi][ni][1] + s_bias[nl + 1]);
            float2 v1 = make_float2(acc[mi][ni][2] + s_bias[nl],
                                    acc[mi][ni][3] + s_bias[nl + 1]);
            *(float2*)(g_gi + (size_t)m * Gsz + n0 + nl) = v0;
            *(float2*)(g_gi + (size_t)(m + 8) * Gsz + n0 + nl) = v1;
        }
    }
}

// ---------------------------------------------------------------------------
// Persistent GRU recurrence, R9: producer-warp pipeline.
// 128 CTAs (8 b-groups x 16 j-tiles), 288 threads:
//   warps 0-7 consumers (4 M-warps x 2 j-warps, register epilogue)
//   warp 8 producer (flag polls + h cp.async, mbarrier handoff)
// No __syncthreads / CP_WAIT / flag polls in the consumer MMA path.
// ---------------------------------------------------------------------------
#define WSPLIT 98304
#define WCHUNK 12288
#define WTOT   196608
#define HBUF   16384
#define HSPLIT 8192
#define PS_SMEM (WTOT + 2 * HBUF)   // 229376

__device__ __forceinline__ void prefetch_gi(int s, int brow0, int brow1, int jcol,
                                            float2 pg[3][2][2]) {
    const float* base = g_gi + (size_t)s * Bsz * Gsz;
#pragma unroll
    for (int g = 0; g < 3; g++) {
#pragma unroll
        for (int ri = 0; ri < 2; ri++) {
            const float* p = base + (size_t)(ri ? brow1 : brow0) * Gsz + g * Hsz + jcol;
            pg[g][ri][0] = *(const float2*)(p);
            pg[g][ri][1] = *(const float2*)(p + 8);
        }
    }
}

__global__ void __launch_bounds__(288) gru_persist_kernel(
    const float* __restrict__ b_hh, const float* __restrict__ W_out,
    const float* __restrict__ b_out, float* __restrict__ out) {
    extern __shared__ __align__(16) char dsm[];
    __shared__ float s_bhh[96];
    __shared__ __align__(8) unsigned long long s_mb[4];   // full0, full1, empty0, empty1
    uint32_t sbase = smem_u32(dsm);
    uint32_t mb_full0 = smem_u32(&s_mb[0]);
    uint32_t mb_full1 = smem_u32(&s_mb[1]);
    uint32_t mb_emp0  = smem_u32(&s_mb[2]);
    uint32_t mb_emp1  = smem_u32(&s_mb[3]);
    int tid = threadIdx.x, wid = tid >> 5, lane = tid & 31;
    int bx = blockIdx.x >> 4, jy = blockIdx.x & 15;
    int b0 = bx * 64, j0 = jy * 32;
    if (tid < 96) s_bhh[tid] = b_hh[(tid >> 5) * Hsz + j0 + (tid & 31)];
    if (tid == 0) {
        MBAR_INIT(mb_full0, 32); MBAR_INIT(mb_full1, 32);
        MBAR_INIT(mb_emp0, 8);   MBAR_INIT(mb_emp1, 8);
    }

    // ---- resident W_hh tile: 12288 x 16B, XOR swizzle (all 288 threads) ----
    for (int i = tid; i < 12288; i += 288) {
        int p = i / 6144;
        int ii = i - p * 6144;
        int c = ii / 768;
        int r2 = ii - c * 768;
        int r = r2 >> 3, u = r2 & 7;
        int g = r >> 5, jr = r & 31;
        const __nv_bfloat16* sp = (p ? g_whh_lo : g_whh_hi) +
            ((size_t)(g * Hsz + j0 + jr)) * Hsz + c * 64 + u * 8;
        uint32_t dst = sbase + (uint32_t)(p * WSPLIT + c * WCHUNK + r * 128 +
                                          ((u ^ (r & 7)) << 4));
        cp16(dst, sp);
    }
    CP_COMMIT();
    CP_WAIT(0);
    __syncthreads();   // only barrier involving all 288 threads

    unsigned int* myflag = &g_flags[bx][jy];
    const unsigned long long* fpair = (const unsigned long long*)&g_flags[bx][0];

    if (wid == 8) {
        // ================= producer warp =================
        int pu0 = 0, pu1 = 0;
        for (int s = 0; s < Ssz; s++) {
            const __nv_bfloat16* ah = g_hb_hi[s & 1];
            const __nv_bfloat16* al = g_hb_lo[s & 1];
            for (int c = 0; c < 8; c++) {
                int q = c & 1;
                uint32_t mb_e = q ? mb_emp1 : mb_emp0;
                uint32_t mb_f = q ? mb_full1 : mb_full0;
                int u = q ? pu1++ : pu0++;
                if (u > 0) MBAR_WAIT(mb_e, (u - 1) & 1);
                poll_pair(fpair + c, (unsigned int)s);
                uint32_t base = sbase + WTOT + (uint32_t)q * HBUF;
                int k0 = c * 64;
                for (int i = lane; i < 1024; i += 32) {
                    int p = i >> 9;
                    int idx = i & 511;
                    int row = idx >> 3, u7 = idx & 7;
                    const __nv_bfloat16* sp = (p ? al : ah) +
                        ((size_t)(b0 + row)) * Hsz + k0 + u7 * 8;
                    uint32_t dst = base + (uint32_t)(p * HSPLIT + row * 128 +
                                                     ((u7 ^ (row & 7)) << 4));
                    cp16(dst, sp);
                }
                CP_ASYNC_MBAR_ARRIVE(mb_f);
            }
        }
        return;   // producer done; consumers finish epilogue/head independently
    }

    // ================= consumer warps (0-7) =================
    const int m_warp = (wid & 3) * 16;     // 4 warps on M (64 rows)
    const int wj = wid >> 2;               // 2 warps on j (16 j's each)
    const int q2 = (lane & 3) * 2;
    const int r0 = m_warp + (lane >> 2);
    const int jb = wj * 16 + q2;
    const int brow0 = b0 + r0, brow1 = b0 + r0 + 8;
    const int jcol = j0 + jb;

    float2 hp[2][2];
#pragma unroll
    for (int ri = 0; ri < 2; ri++)
#pragma unroll
        for (int su = 0; su < 2; su++) hp[ri][su] = make_float2(0.0f, 0.0f);

    float2 pg[3][2][2];
    prefetch_gi(0, brow0, brow1, jcol, pg);

    int cu0 = 0, cu1 = 0;
    for (int s = 0; s < Ssz; s++) {
        float acc[6][4];
#pragma unroll
        for (int ni = 0; ni < 6; ni++)
#pragma unroll
            for (int e = 0; e < 4; e++) acc[ni][e] = 0.0f;

        for (int c = 0; c < 8; c++) {
            int q = c & 1;
            uint32_t mb_f = q ? mb_full1 : mb_full0;
            uint32_t mb_e = q ? mb_emp1 : mb_emp0;
            int u = q ? cu1++ : cu0++;
            MBAR_WAIT(mb_f, u & 1);
            uint32_t hb = sbase + WTOT + (uint32_t)q * HBUF;
            uint32_t wb = sbase + (uint32_t)c * WCHUNK;
#pragma unroll
            for (int kk = 0; kk < 4; kk++) {
                uint32_t fa[2][4];
                {
                    uint32_t arow = (uint32_t)(m_warp + (lane & 15));
                    uint32_t unit = (uint32_t)(kk * 2 + (lane >> 4));
                    uint32_t off = arow * 128 + ((unit ^ (arow & 7)) << 4);
                    LDMX4(fa[0], hb + off);
                    LDMX4(fa[1], hb + HSPLIT + off);
                }
                uint32_t fb[2][3][4];
#pragma unroll
                for (int pp = 0; pp < 3; pp++) {
                    uint32_t brow = (uint32_t)(pp * 32 + wj * 16 + (lane & 7) +
                                               ((lane >> 4) << 3));
                    uint32_t unit = (uint32_t)(kk * 2 + ((lane >> 3) & 1));
                    uint32_t off = brow * 128 + ((unit ^ (brow & 7)) << 4);
                    LDMX4(fb[0][pp], wb + off);
                    LDMX4(fb[1][pp], wb + WSPLIT + off);
                }
#pragma unroll
                for (int t = 0; t < 3; t++) {
                    int sa = (t == 2) ? 1 : 0, sb = (t == 1) ? 1 : 0;
#pragma unroll
                    for (int ni = 0; ni < 6; ni++)
                        MMA_BF16(acc[ni], fa[sa],
                                 fb[sb][ni >> 1][(ni & 1) * 2],
                                 fb[sb][ni >> 1][(ni & 1) * 2 + 1]);
                }
            }
            if (lane == 0) MBAR_ARRIVE(mb_e);   // buffer q free for refill
        }

        // ---- register-resident GRU epilogue ----
        int pout = (s & 1) ^ 1;
        __nv_bfloat16* hho = g_hb_hi[pout];
        __nv_bfloat16* hlo = g_hb_lo[pout];
#pragma unroll
        for (int ri = 0; ri < 2; ri++) {
            int b = ri ? brow1 : brow0;
#pragma unroll
            for (int su = 0; su < 2; su++) {
                float hv[2];
#pragma unroll
                for (int e = 0; e < 2; e++) {
                    float dr = acc[0 * 2 + su][ri * 2 + e] + s_bhh[jb + su * 8 + e];
                    float dz = acc[1 * 2 + su][ri * 2 + e] + s_bhh[32 + jb + su * 8 + e];
                    float dn = acc[2 * 2 + su][ri * 2 + e] + s_bhh[64 + jb + su * 8 + e];
                    float gi_r = e ? pg[0][ri][su].y : pg[0][ri][su].x;
                    float gi_z = e ? pg[1][ri][su].y : pg[1][ri][su].x;
                    float gi_n = e ? pg[2][ri][su].y : pg[2][ri][su].x;
                    float hprev = e ? hp[ri][su].y : hp[ri][su].x;
                    float r = 1.0f / (1.0f + expf(-(gi_r + dr)));
                    float z = 1.0f / (1.0f + expf(-(gi_z + dz)));
                    float n = tanhf(gi_n + r * dn);
                    hv[e] = (1.0f - z) * n + z * hprev;
                }
                hp[ri][su] = make_float2(hv[0], hv[1]);
                int j = jcol + su * 8;
                __nv_bfloat16 h0, l0, h1, l1;
                split2(hv[0], h0, l0);
                split2(hv[1], h1, l1);
                __nv_bfloat162 ph, pl;
                ph.x = h0; ph.y = h1;
                pl.x = l0; pl.y = l1;
                *(__nv_bfloat162*)(hho + (size_t)b * Hsz + j) = ph;
                *(__nv_bfloat162*)(hlo + (size_t)b * Hsz + j) = pl;
                if (s == Ssz - 1)
                    *(float2*)(g_hf + (size_t)b * Hsz + j) = make_float2(hv[0], hv[1]);
            }
        }

        // publish early (consumer-only named barrier), then prefetch next gi
        asm volatile("bar.sync 1, 256;" ::: "memory");
        if (tid == 0) {
            asm volatile("red.release.gpu.global.add.u32 [%0], %1;"
                         :: "l"(myflag), "r"(1u) : "memory");
        }
        if (s + 1 < Ssz) prefetch_gi(s + 1, brow0, brow1, jcol, pg);
    }

    // ---- fused head: jy==0 consumer warps, after all group flags reach Ssz ----
    if (jy == 0) {
#pragma unroll
        for (int c = 0; c < 8; c++) poll_pair(fpair + c, (unsigned int)Ssz);
#pragma unroll 1
        for (int rr = 0; rr < 8; rr++) {
            int b = b0 + (wid << 3) + rr;
            const float* h = g_hf + (size_t)b * Hsz;
            float a8[Lsz];
#pragma unroll
            for (int l = 0; l < Lsz; l++) a8[l] = 0.0f;
            for (int j = lane; j < Hsz; j += 32) {
                float hv = h[j];
#pragma unroll
                for (int l = 0; l < Lsz; l++) a8[l] += hv * W_out[l * Hsz + j];
            }
#pragma unroll
            for (int l = 0; l < Lsz; l++)
#pragma unroll
                for (int o = 16; o > 0; o >>= 1)
                    a8[l] += __shfl_xor_sync(0xffffffff, a8[l], o);
            if (lane == 0) {
                float logits[Lsz], mx = -1e30f, sum = 0.0f;
#pragma unroll
                for (int l = 0; l < Lsz; l++) {
                    logits[l] = a8[l] + b_out[l];
                    mx = fmaxf(mx, logits[l]);
                }
#pragma unroll
                for (int l = 0; l < Lsz; l++) {
                    logits[l] = expf(logits[l] - mx);
                    sum += logits[l];
                }
                float inv = 1.0f / sum;
#pragma unroll
                for (int l = 0; l < Lsz; l++)
                    out[(size_t)b * Lsz + l] = logits[l] * inv;
            }
        }
    }
}

// ---------------------------------------------------------------------------
extern "C" void kernel_launch(void* const* d_in, const int* in_sizes, int n_in,
                              void* d_out, int out_size) {
    const float* x     = (const float*)d_in[0];
    const float* W_ih  = (const float*)d_in[1];
    const float* W_hh  = (const float*)d_in[2];
    const float* b_ih  = (const float*)d_in[3];
    const float* b_hh  = (const float*)d_in[4];
    const float* W_out = (const float*)d_in[5];
    const float* b_out = (const float*)d_in[6];
    float* out = (float*)d_out;

    cudaFuncSetAttribute(gi_mma_kernel, cudaFuncAttributeMaxDynamicSharedMemorySize, GI_SMEM);
    cudaFuncSetAttribute(gru_persist_kernel, cudaFuncAttributeMaxDynamicSharedMemorySize, PS_SMEM);

    prep_kernel<<<34432, 256>>>(x, W_hh, W_ih);
    gi_mma_kernel<<<dim3(Gsz / 128, MROWS / 128), 256, GI_SMEM>>>(b_ih);
    gru_persist_kernel<<<NCTA, 288, PS_SMEM>>>(b_hh, W_out, b_out, out);
}

// round 10
// speedup vs baseline: 1.2580x; 1.2580x over previous
#include <cuda_runtime.h>
#include <cuda_bf16.h>
#include <cstdint>
#include <math.h>

#define Bsz 512
#define Ssz 256
#define Esz 256
#define Hsz 512
#define Gsz 1536
#define Lsz 8
#define MROWS (Ssz * Bsz)
#define NCTA 128

// ---------------- device-global scratch (no runtime alloc) ------------------
__device__ __align__(16) float g_gi[(size_t)MROWS * Gsz];
__device__ __align__(16) float g_hf[Bsz * Hsz];          // final h only
__device__ __align__(16) __nv_bfloat16 g_hb_hi[2][Bsz * Hsz];
__device__ __align__(16) __nv_bfloat16 g_hb_lo[2][Bsz * Hsz];
__device__ __align__(16) __nv_bfloat16 g_x_hi[(size_t)MROWS * Esz];
__device__ __align__(16) __nv_bfloat16 g_x_lo[(size_t)MROWS * Esz];
__device__ __align__(16) __nv_bfloat16 g_whh_hi[Gsz * Hsz];
__device__ __align__(16) __nv_bfloat16 g_whh_lo[Gsz * Hsz];
__device__ __align__(16) __nv_bfloat16 g_wih_hi[Gsz * Esz];
__device__ __align__(16) __nv_bfloat16 g_wih_lo[Gsz * Esz];
__device__ unsigned int g_bars[8 * 32];   // per-b-group counters, 128B apart

// ---------------- PTX helpers (base-target only) -----------------------------
__device__ __forceinline__ uint32_t smem_u32(const void* p) {
    uint32_t a;
    asm("{ .reg .u64 t; cvta.to.shared.u64 t, %1; cvt.u32.u64 %0, t; }" : "=r"(a) : "l"(p));
    return a;
}
__device__ __forceinline__ void cp16(uint32_t dst, const void* src) {
    asm volatile("cp.async.cg.shared.global [%0], [%1], 16;" :: "r"(dst), "l"(src));
}
#define CP_COMMIT() asm volatile("cp.async.commit_group;" ::: "memory")
#define CP_WAIT(n)  asm volatile("cp.async.wait_group %0;" :: "n"(n) : "memory")

#define LDMX4(r, addr) \
    asm volatile("ldmatrix.sync.aligned.m8n8.x4.shared.b16 {%0,%1,%2,%3}, [%4];" \
        : "=r"((r)[0]), "=r"((r)[1]), "=r"((r)[2]), "=r"((r)[3]) : "r"(addr))

#define MMA_BF16(c, a, b0, b1) \
    asm volatile("mma.sync.aligned.m16n8k16.row.col.f32.bf16.bf16.f32 " \
        "{%0,%1,%2,%3}, {%4,%5,%6,%7}, {%8,%9}, {%0,%1,%2,%3};" \
        : "+f"((c)[0]), "+f"((c)[1]), "+f"((c)[2]), "+f"((c)[3]) \
        : "r"((a)[0]), "r"((a)[1]), "r"((a)[2]), "r"((a)[3]), "r"(b0), "r"(b1))

// ---------------- split helpers ----------------------------------------------
__device__ __forceinline__ void split2(float v, __nv_bfloat16& h, __nv_bfloat16& l) {
    h = __float2bfloat16_rn(v);
    l = __float2bfloat16_rn(v - __bfloat162float(h));
}
__device__ __forceinline__ void split_store4(float4 v, __nv_bfloat16* dh, __nv_bfloat16* dl) {
    __nv_bfloat16 h0,l0,h1,l1,h2,l2,h3,l3;
    split2(v.x,h0,l0); split2(v.y,h1,l1); split2(v.z,h2,l2); split2(v.w,h3,l3);
    __nv_bfloat162 p;
    p.x=h0; p.y=h1; ((__nv_bfloat162*)dh)[0]=p;
    p.x=h2; p.y=h3; ((__nv_bfloat162*)dh)[1]=p;
    p.x=l0; p.y=l1; ((__nv_bfloat162*)dl)[0]=p;
    p.x=l2; p.y=l3; ((__nv_bfloat162*)dl)[1]=p;
}

// tiny no-op kernels: shift the ncu capture window onto gru_persist_kernel
__global__ void noop_kernel() {}

// ---------------------------------------------------------------------------
// prep: x split, W_hh split, W_ih split, h0/bars init, one launch
// ---------------------------------------------------------------------------
__global__ void prep_kernel(const float* __restrict__ x,
                            const float* __restrict__ W_hh,
                            const float* __restrict__ W_ih) {
    int blk = blockIdx.x, tid = threadIdx.x;
    if (blk < 32768) {
        size_t t = (size_t)blk * 256 + tid;
        size_t m = t >> 6;
        int e4 = (int)(t & 63) << 2;
        int s = (int)(m >> 9), b = (int)(m & 511);
        float4 v = *(const float4*)(x + ((size_t)b * Ssz + s) * Esz + e4);
        split_store4(v, g_x_hi + m * Esz + e4, g_x_lo + m * Esz + e4);
    } else if (blk < 33536) {
        int t = (blk - 32768) * 256 + tid;
        float4 v = *(const float4*)(W_hh + (size_t)t * 4);
        split_store4(v, g_whh_hi + (size_t)t * 4, g_whh_lo + (size_t)t * 4);
    } else if (blk < 33920) {
        int t = (blk - 33536) * 256 + tid;
        float4 v = *(const float4*)(W_ih + (size_t)t * 4);
        split_store4(v, g_wih_hi + (size_t)t * 4, g_wih_lo + (size_t)t * 4);
    } else {
        int i = (blk - 33920) * 256 + tid;   // < Bsz*Hsz/2
        __nv_bfloat162 z;
        z.x = __float2bfloat16_rn(0.0f); z.y = z.x;
        ((__nv_bfloat162*)g_hb_hi[0])[i] = z;
        ((__nv_bfloat162*)g_hb_lo[0])[i] = z;
        if (blk == 33920 && tid < 256) g_bars[tid] = 0u;
    }
}

// ---------------------------------------------------------------------------
// gi GEMM (HMMA): R7 version (single 72KB buffer, 3 CTAs/SM). Known-good.
// ---------------------------------------------------------------------------
#define GI_SMEM 73728
#define GA_HI 0
#define GA_LO 18432
#define GB_HI 36864
#define GB_LO 55296

__global__ void __launch_bounds__(256) gi_mma_kernel(const float* __restrict__ b_ih) {
    extern __shared__ __align__(16) char dsm[];
    __shared__ float s_bias[128];
    uint32_t sbase = smem_u32(dsm);
    int tid = threadIdx.x, wid = tid >> 5, lane = tid & 31;
    int n0 = blockIdx.x * 128;
    int m0 = blockIdx.y * 128;
    if (tid < 128) s_bias[tid] = b_ih[n0 + tid];

    int m_warp = (wid & 1) * 64;
    int n_warp = (wid >> 1) * 32;

    float acc[4][4][4];
#pragma unroll
    for (int mi = 0; mi < 4; mi++)
#pragma unroll
        for (int ni = 0; ni < 4; ni++)
#pragma unroll
            for (int e = 0; e < 4; e++) acc[mi][ni][e] = 0.0f;

    for (int c = 0; c < 4; c++) {
        int k0 = c * 64;
        for (int i = tid; i < 4096; i += 256) {
            const __nv_bfloat16* sp;
            uint32_t dst;
            int half = (i >> 10) & 1;
            int idx = i & 1023;
            int row = idx >> 3, seg = idx & 7;
            if (i < 2048) {
                sp = (half ? g_x_lo : g_x_hi) + ((size_t)(m0 + row)) * Esz + k0 + seg * 8;
                dst = sbase + (half ? GA_LO : GA_HI) + (uint32_t)(row * 144 + seg * 16);
            } else {
                sp = (half ? g_wih_lo : g_wih_hi) + ((size_t)(n0 + row)) * Esz + k0 + seg * 8;
                dst = sbase + (half ? GB_LO : GB_HI) + (uint32_t)(row * 144 + seg * 16);
            }
            cp16(dst, sp);
        }
        CP_COMMIT();
        CP_WAIT(0);
        __syncthreads();
#pragma unroll
        for (int kk = 0; kk < 4; kk++) {
            int kb = kk * 32;
            uint32_t fa[2][4][4];
#pragma unroll
            for (int mi = 0; mi < 4; mi++) {
                uint32_t arow = (uint32_t)(m_warp + mi * 16 + (lane & 15));
                uint32_t aoff = arow * 144 + kb + ((lane >> 4) << 4);
                LDMX4(fa[0][mi], sbase + GA_HI + aoff);
                LDMX4(fa[1][mi], sbase + GA_LO + aoff);
            }
            uint32_t fb[2][2][4];
#pragma unroll
            for (int p = 0; p < 2; p++) {
                uint32_t brow = (uint32_t)(n_warp + p * 16 + (lane & 7) + ((lane >> 4) << 3));
                uint32_t boff = brow * 144 + kb + (((lane >> 3) & 1) << 4);
                LDMX4(fb[0][p], sbase + GB_HI + boff);
                LDMX4(fb[1][p], sbase + GB_LO + boff);
            }
#pragma unroll
            for (int t = 0; t < 3; t++) {
                int sa = (t == 2) ? 1 : 0, sb = (t == 1) ? 1 : 0;
#pragma unroll
                for (int mi = 0; mi < 4; mi++)
#pragma unroll
                    for (int ni = 0; ni < 4; ni++)
                        MMA_BF16(acc[mi][ni], fa[sa][mi],
                                 fb[sb][ni >> 1][(ni & 1) * 2],
                                 fb[sb][ni >> 1][(ni & 1) * 2 + 1]);
            }
        }
        __syncthreads();
    }

#pragma unroll
    for (int mi = 0; mi < 4; mi++) {
        int m = m0 + m_warp + mi * 16 + (lane >> 2);
#pragma unroll
        for (int ni = 0; ni < 4; ni++) {
            int nl = n_warp + ni * 8 + (lane & 3) * 2;
            float2 v0 = make_float2(acc[mi][ni][0] + s_bias[nl],
                                    acc[mi][ni][1] + s_bias[nl + 1]);
            float2 v1 = make_float2(acc[mi][ni][2] + s_bias[nl],
                                    acc[mi][ni][3] + s_bias[nl + 1]);
            *(float2*)(g_gi + (size_t)m * Gsz + n0 + nl) = v0;
            *(float2*)(g_gi + (size_t)(m + 8) * Gsz + n0 + nl) = v1;
        }
    }
}

// ---------------------------------------------------------------------------
// Persistent GRU recurrence — R7 champion structure, one change: the group
// flag is published immediately after the epilogue sync, BEFORE the gi
// prefetch, so remote consumers unblock ~600 cyc earlier each step.
// 128 CTAs (8 b-groups x 16 j-tiles), 256 threads (4 M-warps x 2 j-warps),
// register-resident epilogue, W_hh tile resident in smem.
// ---------------------------------------------------------------------------
#define WSPLIT 98304
#define WCHUNK 12288
#define WTOT   196608
#define HBUF   16384
#define HSPLIT 8192
#define PS_SMEM (WTOT + 2 * HBUF)   // 229376

__device__ __forceinline__ void prefetch_gi(int s, int brow0, int brow1, int jcol,
                                            float2 pg[3][2][2]) {
    const float* base = g_gi + (size_t)s * Bsz * Gsz;
#pragma unroll
    for (int g = 0; g < 3; g++) {
#pragma unroll
        for (int ri = 0; ri < 2; ri++) {
            const float* p = base + (size_t)(ri ? brow1 : brow0) * Gsz + g * Hsz + jcol;
            pg[g][ri][0] = *(const float2*)(p);
            pg[g][ri][1] = *(const float2*)(p + 8);
        }
    }
}

__global__ void __launch_bounds__(256) gru_persist_kernel(
    const float* __restrict__ b_hh, const float* __restrict__ W_out,
    const float* __restrict__ b_out, float* __restrict__ out) {
    extern __shared__ __align__(16) char dsm[];
    __shared__ float s_bhh[96];
    uint32_t sbase = smem_u32(dsm);
    int tid = threadIdx.x, wid = tid >> 5, lane = tid & 31;
    int bx = blockIdx.x >> 4, jy = blockIdx.x & 15;
    int b0 = bx * 64, j0 = jy * 32;
    if (tid < 96) s_bhh[tid] = b_hh[(tid >> 5) * Hsz + j0 + (tid & 31)];

    // ---- resident W_hh tile: 12288 x 16B, XOR swizzle ----
    for (int i = tid; i < 12288; i += 256) {
        int p = i / 6144;
        int ii = i - p * 6144;
        int c = ii / 768;
        int r2 = ii - c * 768;
        int r = r2 >> 3, u = r2 & 7;
        int g = r >> 5, jr = r & 31;
        const __nv_bfloat16* sp = (p ? g_whh_lo : g_whh_hi) +
            ((size_t)(g * Hsz + j0 + jr)) * Hsz + c * 64 + u * 8;
        uint32_t dst = sbase + (uint32_t)(p * WSPLIT + c * WCHUNK + r * 128 +
                                          ((u ^ (r & 7)) << 4));
        cp16(dst, sp);
    }
    CP_COMMIT();
    CP_WAIT(0);
    __syncthreads();

    const int m_warp = (wid & 3) * 16;     // 4 warps on M (64 rows)
    const int wj = wid >> 2;               // 2 warps on j (16 j's each)
    const int q2 = (lane & 3) * 2;
    const int r0 = m_warp + (lane >> 2);
    const int jb = wj * 16 + q2;
    const int brow0 = b0 + r0, brow1 = b0 + r0 + 8;
    const int jcol = j0 + jb;
    unsigned int* bar = &g_bars[bx * 32];

    float2 hp[2][2];
#pragma unroll
    for (int ri = 0; ri < 2; ri++)
#pragma unroll
        for (int su = 0; su < 2; su++) hp[ri][su] = make_float2(0.0f, 0.0f);

    float2 pg[3][2][2];
    prefetch_gi(0, brow0, brow1, jcol, pg);

    for (int s = 0; s < Ssz; s++) {
        int pin = s & 1, pout = pin ^ 1;
        const __nv_bfloat16* ah = g_hb_hi[pin];
        const __nv_bfloat16* al = g_hb_lo[pin];

        auto issue_h = [&](int c, int q) {
            uint32_t base = sbase + WTOT + (uint32_t)q * HBUF;
            for (int i = tid; i < 1024; i += 256) {
                int p = i >> 9;
                int idx = i & 511;
                int row = idx >> 3, u = idx & 7;
                const __nv_bfloat16* sp = (p ? al : ah) +
                    ((size_t)(b0 + row)) * Hsz + c * 64 + u * 8;
                uint32_t dst = base + (uint32_t)(p * HSPLIT + row * 128 +
                                                 ((u ^ (row & 7)) << 4));
                cp16(dst, sp);
            }
            CP_COMMIT();
        };

        float acc[6][4];
#pragma unroll
        for (int ni = 0; ni < 6; ni++)
#pragma unroll
            for (int e = 0; e < 4; e++) acc[ni][e] = 0.0f;

        issue_h(0, 0);
        for (int c = 0; c < 8; c++) {
            int q = c & 1;
            if (c < 7) { issue_h(c + 1, q ^ 1); CP_WAIT(1); } else { CP_WAIT(0); }
            __syncthreads();
            uint32_t hb = sbase + WTOT + (uint32_t)q * HBUF;
            uint32_t wb = sbase + (uint32_t)c * WCHUNK;
#pragma unroll
            for (int kk = 0; kk < 4; kk++) {
                uint32_t fa[2][4];
                {
                    uint32_t arow = (uint32_t)(m_warp + (lane & 15));
                    uint32_t unit = (uint32_t)(kk * 2 + (lane >> 4));
                    uint32_t off = arow * 128 + ((unit ^ (arow & 7)) << 4);
                    LDMX4(fa[0], hb + off);
                    LDMX4(fa[1], hb + HSPLIT + off);
                }
                uint32_t fb[2][3][4];
#pragma unroll
                for (int pp = 0; pp < 3; pp++) {
                    uint32_t brow = (uint32_t)(pp * 32 + wj * 16 + (lane & 7) +
                                               ((lane >> 4) << 3));
                    uint32_t unit = (uint32_t)(kk * 2 + ((lane >> 3) & 1));
                    uint32_t off = brow * 128 + ((unit ^ (brow & 7)) << 4);
                    LDMX4(fb[0][pp], wb + off);
                    LDMX4(fb[1][pp], wb + WSPLIT + off);
                }
#pragma unroll
                for (int t = 0; t < 3; t++) {
                    int sa = (t == 2) ? 1 : 0, sb = (t == 1) ? 1 : 0;
#pragma unroll
                    for (int ni = 0; ni < 6; ni++)
                        MMA_BF16(acc[ni], fa[sa],
                                 fb[sb][ni >> 1][(ni & 1) * 2],
                                 fb[sb][ni >> 1][(ni & 1) * 2 + 1]);
                }
            }
        }

        // ---- register-resident GRU epilogue ----
        __nv_bfloat16* hho = g_hb_hi[pout];
        __nv_bfloat16* hlo = g_hb_lo[pout];
#pragma unroll
        for (int ri = 0; ri < 2; ri++) {
            int b = ri ? brow1 : brow0;
#pragma unroll
            for (int su = 0; su < 2; su++) {
                float hv[2];
#pragma unroll
                for (int e = 0; e < 2; e++) {
                    float dr = acc[0 * 2 + su][ri * 2 + e] + s_bhh[jb + su * 8 + e];
                    float dz = acc[1 * 2 + su][ri * 2 + e] + s_bhh[32 + jb + su * 8 + e];
                    float dn = acc[2 * 2 + su][ri * 2 + e] + s_bhh[64 + jb + su * 8 + e];
                    float gi_r = e ? pg[0][ri][su].y : pg[0][ri][su].x;
                    float gi_z = e ? pg[1][ri][su].y : pg[1][ri][su].x;
                    float gi_n = e ? pg[2][ri][su].y : pg[2][ri][su].x;
                    float hprev = e ? hp[ri][su].y : hp[ri][su].x;
                    float r = 1.0f / (1.0f + expf(-(gi_r + dr)));
                    float z = 1.0f / (1.0f + expf(-(gi_z + dz)));
                    float n = tanhf(gi_n + r * dn);
                    hv[e] = (1.0f - z) * n + z * hprev;
                }
                hp[ri][su] = make_float2(hv[0], hv[1]);
                int j = jcol + su * 8;
                __nv_bfloat16 h0, l0, h1, l1;
                split2(hv[0], h0, l0);
                split2(hv[1], h1, l1);
                __nv_bfloat162 ph, pl;
                ph.x = h0; ph.y = h1;
                pl.x = l0; pl.y = l1;
                *(__nv_bfloat162*)(hho + (size_t)b * Hsz + j) = ph;
                *(__nv_bfloat162*)(hlo + (size_t)b * Hsz + j) = pl;
                if (s == Ssz - 1)
                    *(float2*)(g_hf + (size_t)b * Hsz + j) = make_float2(hv[0], hv[1]);
            }
        }

        // ---- publish FIRST (all h stores are pre-sync), then prefetch gi ----
        __syncthreads();
        if (tid == 0) {
            asm volatile("red.release.gpu.global.add.u32 [%0], %1;"
                         :: "l"(bar), "r"(1u) : "memory");
        }
        if (s + 1 < Ssz) prefetch_gi(s + 1, brow0, brow1, jcol, pg);

        // ---- per-b-group barrier wait ----
        if (tid == 0) {
            unsigned int target = (unsigned int)(s + 1) * 16u;
            unsigned int v;
            do {
                asm volatile("ld.acquire.gpu.u32 %0, [%1];" : "=r"(v) : "l"(bar));
            } while (v < target);
        }
        __syncthreads();
    }

    // ---- fused head: jy==0 CTAs compute logits+softmax for rows b0..b0+63 ----
    if (jy == 0) {
#pragma unroll 1
        for (int rr = 0; rr < 8; rr++) {
            int b = b0 + (wid << 3) + rr;
            const float* h = g_hf + (size_t)b * Hsz;
            float a8[Lsz];
#pragma unroll
            for (int l = 0; l < Lsz; l++) a8[l] = 0.0f;
            for (int j = lane; j < Hsz; j += 32) {
                float hv = h[j];
#pragma unroll
                for (int l = 0; l < Lsz; l++) a8[l] += hv * W_out[l * Hsz + j];
            }
#pragma unroll
            for (int l = 0; l < Lsz; l++)
#pragma unroll
                for (int o = 16; o > 0; o >>= 1)
                    a8[l] += __shfl_xor_sync(0xffffffff, a8[l], o);
            if (lane == 0) {
                float logits[Lsz], mx = -1e30f, sum = 0.0f;
#pragma unroll
                for (int l = 0; l < Lsz; l++) {
                    logits[l] = a8[l] + b_out[l];
                    mx = fmaxf(mx, logits[l]);
                }
#pragma unroll
                for (int l = 0; l < Lsz; l++) {
                    logits[l] = expf(logits[l] - mx);
                    sum += logits[l];
                }
                float inv = 1.0f / sum;
#pragma unroll
                for (int l = 0; l < Lsz; l++)
                    out[(size_t)b * Lsz + l] = logits[l] * inv;
            }
        }
    }
}

// ---------------------------------------------------------------------------
extern "C" void kernel_launch(void* const* d_in, const int* in_sizes, int n_in,
                              void* d_out, int out_size) {
    const float* x     = (const float*)d_in[0];
    const float* W_ih  = (const float*)d_in[1];
    const float* W_hh  = (const float*)d_in[2];
    const float* b_ih  = (const float*)d_in[3];
    const float* b_hh  = (const float*)d_in[4];
    const float* W_out = (const float*)d_in[5];
    const float* b_out = (const float*)d_in[6];
    float* out = (float*)d_out;

    cudaFuncSetAttribute(gi_mma_kernel, cudaFuncAttributeMaxDynamicSharedMemorySize, GI_SMEM);
    cudaFuncSetAttribute(gru_persist_kernel, cudaFuncAttributeMaxDynamicSharedMemorySize, PS_SMEM);

    // launch sequence padded with no-ops so the ncu -s5-c1 window (which has
    // been landing on prep each round) has a shot at gru_persist_kernel.
    noop_kernel<<<1, 32>>>();
    prep_kernel<<<34432, 256>>>(x, W_hh, W_ih);
    gi_mma_kernel<<<dim3(Gsz / 128, MROWS / 128), 256, GI_SMEM>>>(b_ih);
    gru_persist_kernel<<<NCTA, 256, PS_SMEM>>>(b_hh, W_out, b_out, out);
    noop_kernel<<<1, 32>>>();
    noop_kernel<<<1, 32>>>();
}

// round 11
// speedup vs baseline: 1.2825x; 1.0194x over previous
#include <cuda_runtime.h>
#include <cuda_bf16.h>
#include <cstdint>
#include <math.h>

#define Bsz 512
#define Ssz 256
#define Esz 256
#define Hsz 512
#define Gsz 1536
#define Lsz 8
#define MROWS (Ssz * Bsz)
#define NCTA 128

// ---------------- device-global scratch (no runtime alloc) ------------------
__device__ __align__(16) float g_gi[(size_t)MROWS * Gsz];
__device__ __align__(16) float g_hf[Bsz * Hsz];          // final h only
__device__ __align__(16) __nv_bfloat16 g_hb_hi[2][Bsz * Hsz];
__device__ __align__(16) __nv_bfloat16 g_hb_lo[2][Bsz * Hsz];
__device__ __align__(16) __nv_bfloat16 g_x_hi[(size_t)MROWS * Esz];
__device__ __align__(16) __nv_bfloat16 g_x_lo[(size_t)MROWS * Esz];
__device__ __align__(16) __nv_bfloat16 g_whh_hi[Gsz * Hsz];
__device__ __align__(16) __nv_bfloat16 g_whh_lo[Gsz * Hsz];
__device__ __align__(16) __nv_bfloat16 g_wih_hi[Gsz * Esz];
__device__ __align__(16) __nv_bfloat16 g_wih_lo[Gsz * Esz];
__device__ unsigned int g_bars[8 * 32];   // per-b-group counters, 128B apart

// ---------------- PTX helpers (base-target only) -----------------------------
__device__ __forceinline__ uint32_t smem_u32(const void* p) {
    uint32_t a;
    asm("{ .reg .u64 t; cvta.to.shared.u64 t, %1; cvt.u32.u64 %0, t; }" : "=r"(a) : "l"(p));
    return a;
}
__device__ __forceinline__ void cp16(uint32_t dst, const void* src) {
    asm volatile("cp.async.cg.shared.global [%0], [%1], 16;" :: "r"(dst), "l"(src));
}
#define CP_COMMIT() asm volatile("cp.async.commit_group;" ::: "memory")
#define CP_WAIT(n)  asm volatile("cp.async.wait_group %0;" :: "n"(n) : "memory")

#define LDMX4(r, addr) \
    asm volatile("ldmatrix.sync.aligned.m8n8.x4.shared.b16 {%0,%1,%2,%3}, [%4];" \
        : "=r"((r)[0]), "=r"((r)[1]), "=r"((r)[2]), "=r"((r)[3]) : "r"(addr))

#define MMA_BF16(c, a, b0, b1) \
    asm volatile("mma.sync.aligned.m16n8k16.row.col.f32.bf16.bf16.f32 " \
        "{%0,%1,%2,%3}, {%4,%5,%6,%7}, {%8,%9}, {%0,%1,%2,%3};" \
        : "+f"((c)[0]), "+f"((c)[1]), "+f"((c)[2]), "+f"((c)[3]) \
        : "r"((a)[0]), "r"((a)[1]), "r"((a)[2]), "r"((a)[3]), "r"(b0), "r"(b1))

// ---------------- split helpers ----------------------------------------------
__device__ __forceinline__ void split2(float v, __nv_bfloat16& h, __nv_bfloat16& l) {
    h = __float2bfloat16_rn(v);
    l = __float2bfloat16_rn(v - __bfloat162float(h));
}
__device__ __forceinline__ void split_store4(float4 v, __nv_bfloat16* dh, __nv_bfloat16* dl) {
    __nv_bfloat16 h0,l0,h1,l1,h2,l2,h3,l3;
    split2(v.x,h0,l0); split2(v.y,h1,l1); split2(v.z,h2,l2); split2(v.w,h3,l3);
    __nv_bfloat162 p;
    p.x=h0; p.y=h1; ((__nv_bfloat162*)dh)[0]=p;
    p.x=h2; p.y=h3; ((__nv_bfloat162*)dh)[1]=p;
    p.x=l0; p.y=l1; ((__nv_bfloat162*)dl)[0]=p;
    p.x=l2; p.y=l3; ((__nv_bfloat162*)dl)[1]=p;
}

// tiny no-op kernels: keep the ncu capture window on gru_persist_kernel
__global__ void noop_kernel() {}

// ---------------------------------------------------------------------------
// prep: x split, W_hh split, W_ih split, h0/bars init, one launch
// ---------------------------------------------------------------------------
__global__ void prep_kernel(const float* __restrict__ x,
                            const float* __restrict__ W_hh,
                            const float* __restrict__ W_ih) {
    int blk = blockIdx.x, tid = threadIdx.x;
    if (blk < 32768) {
        size_t t = (size_t)blk * 256 + tid;
        size_t m = t >> 6;
        int e4 = (int)(t & 63) << 2;
        int s = (int)(m >> 9), b = (int)(m & 511);
        float4 v = *(const float4*)(x + ((size_t)b * Ssz + s) * Esz + e4);
        split_store4(v, g_x_hi + m * Esz + e4, g_x_lo + m * Esz + e4);
    } else if (blk < 33536) {
        int t = (blk - 32768) * 256 + tid;
        float4 v = *(const float4*)(W_hh + (size_t)t * 4);
        split_store4(v, g_whh_hi + (size_t)t * 4, g_whh_lo + (size_t)t * 4);
    } else if (blk < 33920) {
        int t = (blk - 33536) * 256 + tid;
        float4 v = *(const float4*)(W_ih + (size_t)t * 4);
        split_store4(v, g_wih_hi + (size_t)t * 4, g_wih_lo + (size_t)t * 4);
    } else {
        int i = (blk - 33920) * 256 + tid;   // < Bsz*Hsz/2
        __nv_bfloat162 z;
        z.x = __float2bfloat16_rn(0.0f); z.y = z.x;
        ((__nv_bfloat162*)g_hb_hi[0])[i] = z;
        ((__nv_bfloat162*)g_hb_lo[0])[i] = z;
        if (blk == 33920 && tid < 256) g_bars[tid] = 0u;
    }
}

// ---------------------------------------------------------------------------
// gi GEMM (HMMA): R7 version (single 72KB buffer, 3 CTAs/SM). Known-good.
// ---------------------------------------------------------------------------
#define GI_SMEM 73728
#define GA_HI 0
#define GA_LO 18432
#define GB_HI 36864
#define GB_LO 55296

__global__ void __launch_bounds__(256) gi_mma_kernel(const float* __restrict__ b_ih) {
    extern __shared__ __align__(16) char dsm[];
    __shared__ float s_bias[128];
    uint32_t sbase = smem_u32(dsm);
    int tid = threadIdx.x, wid = tid >> 5, lane = tid & 31;
    int n0 = blockIdx.x * 128;
    int m0 = blockIdx.y * 128;
    if (tid < 128) s_bias[tid] = b_ih[n0 + tid];

    int m_warp = (wid & 1) * 64;
    int n_warp = (wid >> 1) * 32;

    float acc[4][4][4];
#pragma unroll
    for (int mi = 0; mi < 4; mi++)
#pragma unroll
        for (int ni = 0; ni < 4; ni++)
#pragma unroll
            for (int e = 0; e < 4; e++) acc[mi][ni][e] = 0.0f;

    for (int c = 0; c < 4; c++) {
        int k0 = c * 64;
        for (int i = tid; i < 4096; i += 256) {
            const __nv_bfloat16* sp;
            uint32_t dst;
            int half = (i >> 10) & 1;
            int idx = i & 1023;
            int row = idx >> 3, seg = idx & 7;
            if (i < 2048) {
                sp = (half ? g_x_lo : g_x_hi) + ((size_t)(m0 + row)) * Esz + k0 + seg * 8;
                dst = sbase + (half ? GA_LO : GA_HI) + (uint32_t)(row * 144 + seg * 16);
            } else {
                sp = (half ? g_wih_lo : g_wih_hi) + ((size_t)(n0 + row)) * Esz + k0 + seg * 8;
                dst = sbase + (half ? GB_LO : GB_HI) + (uint32_t)(row * 144 + seg * 16);
            }
            cp16(dst, sp);
        }
        CP_COMMIT();
        CP_WAIT(0);
        __syncthreads();
#pragma unroll
        for (int kk = 0; kk < 4; kk++) {
            int kb = kk * 32;
            uint32_t fa[2][4][4];
#pragma unroll
            for (int mi = 0; mi < 4; mi++) {
                uint32_t arow = (uint32_t)(m_warp + mi * 16 + (lane & 15));
                uint32_t aoff = arow * 144 + kb + ((lane >> 4) << 4);
                LDMX4(fa[0][mi], sbase + GA_HI + aoff);
                LDMX4(fa[1][mi], sbase + GA_LO + aoff);
            }
            uint32_t fb[2][2][4];
#pragma unroll
            for (int p = 0; p < 2; p++) {
                uint32_t brow = (uint32_t)(n_warp + p * 16 + (lane & 7) + ((lane >> 4) << 3));
                uint32_t boff = brow * 144 + kb + (((lane >> 3) & 1) << 4);
                LDMX4(fb[0][p], sbase + GB_HI + boff);
                LDMX4(fb[1][p], sbase + GB_LO + boff);
            }
#pragma unroll
            for (int t = 0; t < 3; t++) {
                int sa = (t == 2) ? 1 : 0, sb = (t == 1) ? 1 : 0;
#pragma unroll
                for (int mi = 0; mi < 4; mi++)
#pragma unroll
                    for (int ni = 0; ni < 4; ni++)
                        MMA_BF16(acc[mi][ni], fa[sa][mi],
                                 fb[sb][ni >> 1][(ni & 1) * 2],
                                 fb[sb][ni >> 1][(ni & 1) * 2 + 1]);
            }
        }
        __syncthreads();
    }

#pragma unroll
    for (int mi = 0; mi < 4; mi++) {
        int m = m0 + m_warp + mi * 16 + (lane >> 2);
#pragma unroll
        for (int ni = 0; ni < 4; ni++) {
            int nl = n_warp + ni * 8 + (lane & 3) * 2;
            float2 v0 = make_float2(acc[mi][ni][0] + s_bias[nl],
                                    acc[mi][ni][1] + s_bias[nl + 1]);
            float2 v1 = make_float2(acc[mi][ni][2] + s_bias[nl],
                                    acc[mi][ni][3] + s_bias[nl + 1]);
            *(float2*)(g_gi + (size_t)m * Gsz + n0 + nl) = v0;
            *(float2*)(g_gi + (size_t)(m + 8) * Gsz + n0 + nl) = v1;
        }
    }
}

// ---------------------------------------------------------------------------
// Persistent GRU recurrence — R10 champion + (a) kk-level fragment double
// buffering (prefetch next kk's LDSM while current kk's MMAs issue) to hide
// LDSM->MMA latency (profile: tensor 38.8%, L1 44%, both unsaturated), and
// (b) fast-math sigmoid (__expf + __fdividef) in the epilogue.
// ---------------------------------------------------------------------------
#define WSPLIT 98304
#define WCHUNK 12288
#define WTOT   196608
#define HBUF   16384
#define HSPLIT 8192
#define PS_SMEM (WTOT + 2 * HBUF)   // 229376

__device__ __forceinline__ void prefetch_gi(int s, int brow0, int brow1, int jcol,
                                            float2 pg[3][2][2]) {
    const float* base = g_gi + (size_t)s * Bsz * Gsz;
#pragma unroll
    for (int g = 0; g < 3; g++) {
#pragma unroll
        for (int ri = 0; ri < 2; ri++) {
            const float* p = base + (size_t)(ri ? brow1 : brow0) * Gsz + g * Hsz + jcol;
            pg[g][ri][0] = *(const float2*)(p);
            pg[g][ri][1] = *(const float2*)(p + 8);
        }
    }
}

__global__ void __launch_bounds__(256) gru_persist_kernel(
    const float* __restrict__ b_hh, const float* __restrict__ W_out,
    const float* __restrict__ b_out, float* __restrict__ out) {
    extern __shared__ __align__(16) char dsm[];
    __shared__ float s_bhh[96];
    uint32_t sbase = smem_u32(dsm);
    int tid = threadIdx.x, wid = tid >> 5, lane = tid & 31;
    int bx = blockIdx.x >> 4, jy = blockIdx.x & 15;
    int b0 = bx * 64, j0 = jy * 32;
    if (tid < 96) s_bhh[tid] = b_hh[(tid >> 5) * Hsz + j0 + (tid & 31)];

    // ---- resident W_hh tile: 12288 x 16B, XOR swizzle ----
    for (int i = tid; i < 12288; i += 256) {
        int p = i / 6144;
        int ii = i - p * 6144;
        int c = ii / 768;
        int r2 = ii - c * 768;
        int r = r2 >> 3, u = r2 & 7;
        int g = r >> 5, jr = r & 31;
        const __nv_bfloat16* sp = (p ? g_whh_lo : g_whh_hi) +
            ((size_t)(g * Hsz + j0 + jr)) * Hsz + c * 64 + u * 8;
        uint32_t dst = sbase + (uint32_t)(p * WSPLIT + c * WCHUNK + r * 128 +
                                          ((u ^ (r & 7)) << 4));
        cp16(dst, sp);
    }
    CP_COMMIT();
    CP_WAIT(0);
    __syncthreads();

    const int m_warp = (wid & 3) * 16;     // 4 warps on M (64 rows)
    const int wj = wid >> 2;               // 2 warps on j (16 j's each)
    const int q2 = (lane & 3) * 2;
    const int r0 = m_warp + (lane >> 2);
    const int jb = wj * 16 + q2;
    const int brow0 = b0 + r0, brow1 = b0 + r0 + 8;
    const int jcol = j0 + jb;
    unsigned int* bar = &g_bars[bx * 32];

    // precomputed LDSM address components (row parts are kk-invariant)
    const uint32_t arow = (uint32_t)(m_warp + (lane & 15));
    const uint32_t a_ub = (uint32_t)(lane >> 4);           // unit base for A
    const uint32_t a_rowoff = arow * 128;
    const uint32_t a_rx = arow & 7;
    uint32_t b_rowoff[3], b_rx[3];
#pragma unroll
    for (int pp = 0; pp < 3; pp++) {
        uint32_t brow = (uint32_t)(pp * 32 + wj * 16 + (lane & 7) + ((lane >> 4) << 3));
        b_rowoff[pp] = brow * 128;
        b_rx[pp] = brow & 7;
    }
    const uint32_t b_ub = (uint32_t)((lane >> 3) & 1);

    float2 hp[2][2];
#pragma unroll
    for (int ri = 0; ri < 2; ri++)
#pragma unroll
        for (int su = 0; su < 2; su++) hp[ri][su] = make_float2(0.0f, 0.0f);

    float2 pg[3][2][2];
    prefetch_gi(0, brow0, brow1, jcol, pg);

    for (int s = 0; s < Ssz; s++) {
        int pin = s & 1, pout = pin ^ 1;
        const __nv_bfloat16* ah = g_hb_hi[pin];
        const __nv_bfloat16* al = g_hb_lo[pin];

        auto issue_h = [&](int c, int q) {
            uint32_t base = sbase + WTOT + (uint32_t)q * HBUF;
            for (int i = tid; i < 1024; i += 256) {
                int p = i >> 9;
                int idx = i & 511;
                int row = idx >> 3, u = idx & 7;
                const __nv_bfloat16* sp = (p ? al : ah) +
                    ((size_t)(b0 + row)) * Hsz + c * 64 + u * 8;
                uint32_t dst = base + (uint32_t)(p * HSPLIT + row * 128 +
                                                 ((u ^ (row & 7)) << 4));
                cp16(dst, sp);
            }
            CP_COMMIT();
        };

        float acc[6][4];
#pragma unroll
        for (int ni = 0; ni < 6; ni++)
#pragma unroll
            for (int e = 0; e < 4; e++) acc[ni][e] = 0.0f;

        issue_h(0, 0);
        for (int c = 0; c < 8; c++) {
            int q = c & 1;
            if (c < 7) { issue_h(c + 1, q ^ 1); CP_WAIT(1); } else { CP_WAIT(0); }
            __syncthreads();
            uint32_t hb = sbase + WTOT + (uint32_t)q * HBUF;
            uint32_t wb = sbase + (uint32_t)c * WCHUNK;

            // fragment double buffer: [buf][split][...]
            uint32_t fa[2][2][4];
            uint32_t fb[2][2][3][4];

            auto load_frags = [&](int kk, int fq) {
                uint32_t ua = (uint32_t)(kk * 2) + a_ub;
                uint32_t offa = a_rowoff + ((ua ^ a_rx) << 4);
                LDMX4(fa[fq][0], hb + offa);
                LDMX4(fa[fq][1], hb + HSPLIT + offa);
                uint32_t ub = (uint32_t)(kk * 2) + b_ub;
#pragma unroll
                for (int pp = 0; pp < 3; pp++) {
                    uint32_t offb = b_rowoff[pp] + ((ub ^ b_rx[pp]) << 4);
                    LDMX4(fb[fq][0][pp], wb + offb);
                    LDMX4(fb[fq][1][pp], wb + WSPLIT + offb);
                }
            };

            load_frags(0, 0);
#pragma unroll
            for (int kk = 0; kk < 4; kk++) {
                int fq = kk & 1;
                if (kk < 3) load_frags(kk + 1, fq ^ 1);
#pragma unroll
                for (int t = 0; t < 3; t++) {
                    int sa = (t == 2) ? 1 : 0, sb = (t == 1) ? 1 : 0;
#pragma unroll
                    for (int ni = 0; ni < 6; ni++)
                        MMA_BF16(acc[ni], fa[fq][sa],
                                 fb[fq][sb][ni >> 1][(ni & 1) * 2],
                                 fb[fq][sb][ni >> 1][(ni & 1) * 2 + 1]);
                }
            }
        }

        // ---- register-resident GRU epilogue (fast-math sigmoid) ----
        __nv_bfloat16* hho = g_hb_hi[pout];
        __nv_bfloat16* hlo = g_hb_lo[pout];
#pragma unroll
        for (int ri = 0; ri < 2; ri++) {
            int b = ri ? brow1 : brow0;
#pragma unroll
            for (int su = 0; su < 2; su++) {
                float hv[2];
#pragma unroll
                for (int e = 0; e < 2; e++) {
                    float dr = acc[0 * 2 + su][ri * 2 + e] + s_bhh[jb + su * 8 + e];
                    float dz = acc[1 * 2 + su][ri * 2 + e] + s_bhh[32 + jb + su * 8 + e];
                    float dn = acc[2 * 2 + su][ri * 2 + e] + s_bhh[64 + jb + su * 8 + e];
                    float gi_r = e ? pg[0][ri][su].y : pg[0][ri][su].x;
                    float gi_z = e ? pg[1][ri][su].y : pg[1][ri][su].x;
                    float gi_n = e ? pg[2][ri][su].y : pg[2][ri][su].x;
                    float hprev = e ? hp[ri][su].y : hp[ri][su].x;
                    float r = __fdividef(1.0f, 1.0f + __expf(-(gi_r + dr)));
                    float z = __fdividef(1.0f, 1.0f + __expf(-(gi_z + dz)));
                    float n = tanhf(gi_n + r * dn);
                    hv[e] = (1.0f - z) * n + z * hprev;
                }
                hp[ri][su] = make_float2(hv[0], hv[1]);
                int j = jcol + su * 8;
                __nv_bfloat16 h0, l0, h1, l1;
                split2(hv[0], h0, l0);
                split2(hv[1], h1, l1);
                __nv_bfloat162 ph, pl;
                ph.x = h0; ph.y = h1;
                pl.x = l0; pl.y = l1;
                *(__nv_bfloat162*)(hho + (size_t)b * Hsz + j) = ph;
                *(__nv_bfloat162*)(hlo + (size_t)b * Hsz + j) = pl;
                if (s == Ssz - 1)
                    *(float2*)(g_hf + (size_t)b * Hsz + j) = make_float2(hv[0], hv[1]);
            }
        }

        // ---- publish FIRST (all h stores are pre-sync), then prefetch gi ----
        __syncthreads();
        if (tid == 0) {
            asm volatile("red.release.gpu.global.add.u32 [%0], %1;"
                         :: "l"(bar), "r"(1u) : "memory");
        }
        if (s + 1 < Ssz) prefetch_gi(s + 1, brow0, brow1, jcol, pg);

        // ---- per-b-group barrier wait ----
        if (tid == 0) {
            unsigned int target = (unsigned int)(s + 1) * 16u;
            unsigned int v;
            do {
                asm volatile("ld.acquire.gpu.u32 %0, [%1];" : "=r"(v) : "l"(bar));
            } while (v < target);
        }
        __syncthreads();
    }

    // ---- fused head: jy==0 CTAs compute logits+softmax for rows b0..b0+63 ----
    if (jy == 0) {
#pragma unroll 1
        for (int rr = 0; rr < 8; rr++) {
            int b = b0 + (wid << 3) + rr;
            const float* h = g_hf + (size_t)b * Hsz;
            float a8[Lsz];
#pragma unroll
            for (int l = 0; l < Lsz; l++) a8[l] = 0.0f;
            for (int j = lane; j < Hsz; j += 32) {
                float hv = h[j];
#pragma unroll
                for (int l = 0; l < Lsz; l++) a8[l] += hv * W_out[l * Hsz + j];
            }
#pragma unroll
            for (int l = 0; l < Lsz; l++)
#pragma unroll
                for (int o = 16; o > 0; o >>= 1)
                    a8[l] += __shfl_xor_sync(0xffffffff, a8[l], o);
            if (lane == 0) {
                float logits[Lsz], mx = -1e30f, sum = 0.0f;
#pragma unroll
                for (int l = 0; l < Lsz; l++) {
                    logits[l] = a8[l] + b_out[l];
                    mx = fmaxf(mx, logits[l]);
                }
#pragma unroll
                for (int l = 0; l < Lsz; l++) {
                    logits[l] = expf(logits[l] - mx);
                    sum += logits[l];
                }
                float inv = 1.0f / sum;
#pragma unroll
                for (int l = 0; l < Lsz; l++)
                    out[(size_t)b * Lsz + l] = logits[l] * inv;
            }
        }
    }
}

// ---------------------------------------------------------------------------
extern "C" void kernel_launch(void* const* d_in, const int* in_sizes, int n_in,
                              void* d_out, int out_size) {
    const float* x     = (const float*)d_in[0];
    const float* W_ih  = (const float*)d_in[1];
    const float* W_hh  = (const float*)d_in[2];
    const float* b_ih  = (const float*)d_in[3];
    const float* b_hh  = (const float*)d_in[4];
    const float* W_out = (const float*)d_in[5];
    const float* b_out = (const float*)d_in[6];
    float* out = (float*)d_out;

    cudaFuncSetAttribute(gi_mma_kernel, cudaFuncAttributeMaxDynamicSharedMemorySize, GI_SMEM);
    cudaFuncSetAttribute(gru_persist_kernel, cudaFuncAttributeMaxDynamicSharedMemorySize, PS_SMEM);

    // identical launch sequence to R10 so the ncu window stays on gru
    noop_kernel<<<1, 32>>>();
    prep_kernel<<<34432, 256>>>(x, W_hh, W_ih);
    gi_mma_kernel<<<dim3(Gsz / 128, MROWS / 128), 256, GI_SMEM>>>(b_ih);
    gru_persist_kernel<<<NCTA, 256, PS_SMEM>>>(b_hh, W_out, b_out, out);
    noop_kernel<<<1, 32>>>();
    noop_kernel<<<1, 32>>>();
}